// round 2
// baseline (speedup 1.0000x reference)
#include <cuda_runtime.h>
#include <math.h>

// Problem constants (fixed shapes for CLIPLoss_22359599743077)
#define N 8192
#define D 1024
#define BM 128
#define BN 128
#define BK 16
#define NT (N / BN)   // 64 tiles per dimension

// ---------------------------------------------------------------------------
// Scratch: __device__ globals (no allocation allowed in kernel_launch).
// Per-tile online-softmax partials for rows (i2t direction) and cols (t2i).
// Layout: part[row * NT + tileIdx]
// ---------------------------------------------------------------------------
__device__ float  g_rowM[N * NT];
__device__ float  g_rowS[N * NT];
__device__ float  g_colM[N * NT];
__device__ float  g_colS[N * NT];
__device__ float  g_diag[N];
__device__ double g_acc;

__global__ void init_kernel() { g_acc = 0.0; }

// ---------------------------------------------------------------------------
// Fused GEMM + per-tile logsumexp partials.
// C_tile = scale * A[by*128 .. ][:] @ B[bx*128 .. ][:]^T  (both row-major [N,D])
// Emits (max, sumexp) per tile-row and per tile-col; never writes logits.
// ---------------------------------------------------------------------------
__global__ void __launch_bounds__(256)
gemm_lse_kernel(const float* __restrict__ A, const float* __restrict__ B,
                const float* __restrict__ scale_p) {
    __shared__ float As[BK][BM + 4];
    __shared__ float Bs[BK][BN + 4];
    __shared__ float red[16][BN];
    __shared__ float colMax[BN];

    const int tid = threadIdx.x;
    const int tx = tid & 15;   // column group (owns cols tx*8 .. tx*8+7)
    const int ty = tid >> 4;   // row group    (owns rows ty*8 .. ty*8+7)

    const float* Ab = A + (size_t)blockIdx.y * BM * D;
    const float* Bb = B + (size_t)blockIdx.x * BN * D;

    float acc[8][8];
#pragma unroll
    for (int m = 0; m < 8; m++)
#pragma unroll
        for (int n = 0; n < 8; n++) acc[m][n] = 0.0f;

    for (int k0 = 0; k0 < D; k0 += BK) {
        // Cooperative load: 128 rows x 16 k each for A and B, float4 per thread x2.
#pragma unroll
        for (int l = 0; l < 2; l++) {
            int idx = tid + l * 256;        // 0..511
            int row = idx >> 2;             // 0..127
            int kq  = idx & 3;              // float4 slot within BK
            float4 va = *(const float4*)(Ab + (size_t)row * D + k0 + kq * 4);
            As[kq * 4 + 0][row] = va.x;
            As[kq * 4 + 1][row] = va.y;
            As[kq * 4 + 2][row] = va.z;
            As[kq * 4 + 3][row] = va.w;
            float4 vb = *(const float4*)(Bb + (size_t)row * D + k0 + kq * 4);
            Bs[kq * 4 + 0][row] = vb.x;
            Bs[kq * 4 + 1][row] = vb.y;
            Bs[kq * 4 + 2][row] = vb.z;
            Bs[kq * 4 + 3][row] = vb.w;
        }
        __syncthreads();

#pragma unroll
        for (int k = 0; k < BK; k++) {
            float4 a0 = *(const float4*)&As[k][ty * 8];
            float4 a1 = *(const float4*)&As[k][ty * 8 + 4];
            float4 b0 = *(const float4*)&Bs[k][tx * 8];
            float4 b1 = *(const float4*)&Bs[k][tx * 8 + 4];
            float af[8] = {a0.x, a0.y, a0.z, a0.w, a1.x, a1.y, a1.z, a1.w};
            float bf[8] = {b0.x, b0.y, b0.z, b0.w, b1.x, b1.y, b1.z, b1.w};
#pragma unroll
            for (int m = 0; m < 8; m++)
#pragma unroll
                for (int n = 0; n < 8; n++)
                    acc[m][n] = fmaf(af[m], bf[n], acc[m][n]);
        }
        __syncthreads();
    }

    // Scale to logits
    const float scale = *scale_p;
#pragma unroll
    for (int m = 0; m < 8; m++)
#pragma unroll
        for (int n = 0; n < 8; n++) acc[m][n] *= scale;

    // ---- Row partials: row r = ty*8+m is shared by the 16 threads with the
    // same ty (contiguous 16 lanes inside one warp) -> xor-shuffle reduce.
#pragma unroll
    for (int m = 0; m < 8; m++) {
        float lm = acc[m][0];
#pragma unroll
        for (int n = 1; n < 8; n++) lm = fmaxf(lm, acc[m][n]);
#pragma unroll
        for (int off = 1; off < 16; off <<= 1)
            lm = fmaxf(lm, __shfl_xor_sync(0xffffffffu, lm, off));
        float ls = 0.0f;
#pragma unroll
        for (int n = 0; n < 8; n++) ls += expf(acc[m][n] - lm);
#pragma unroll
        for (int off = 1; off < 16; off <<= 1)
            ls += __shfl_xor_sync(0xffffffffu, ls, off);
        if (tx == 0) {
            int r = blockIdx.y * BM + ty * 8 + m;
            g_rowM[(size_t)r * NT + blockIdx.x] = lm;
            g_rowS[(size_t)r * NT + blockIdx.x] = ls;
        }
    }

    // ---- Col partials: col c = tx*8+n spans all 16 ty groups -> smem reduce.
#pragma unroll
    for (int n = 0; n < 8; n++) {
        float lm = acc[0][n];
#pragma unroll
        for (int m = 1; m < 8; m++) lm = fmaxf(lm, acc[m][n]);
        red[ty][tx * 8 + n] = lm;
    }
    __syncthreads();
    if (tid < BN) {
        float m0 = red[0][tid];
#pragma unroll
        for (int t = 1; t < 16; t++) m0 = fmaxf(m0, red[t][tid]);
        colMax[tid] = m0;
    }
    __syncthreads();
#pragma unroll
    for (int n = 0; n < 8; n++) {
        float cm = colMax[tx * 8 + n];
        float ls = 0.0f;
#pragma unroll
        for (int m = 0; m < 8; m++) ls += expf(acc[m][n] - cm);
        red[ty][tx * 8 + n] = ls;
    }
    __syncthreads();
    if (tid < BN) {
        float s = 0.0f;
#pragma unroll
        for (int t = 0; t < 16; t++) s += red[t][tid];
        int c = blockIdx.x * BN + tid;
        g_colM[(size_t)c * NT + blockIdx.y] = colMax[tid];
        g_colS[(size_t)c * NT + blockIdx.y] = s;
    }
}

// ---------------------------------------------------------------------------
// Diagonal: diag[i] = scale * dot(img[i], txt[i]). One warp per row.
// ---------------------------------------------------------------------------
__global__ void diag_kernel(const float* __restrict__ A, const float* __restrict__ B,
                            const float* __restrict__ scale_p) {
    int warp = (blockIdx.x * blockDim.x + threadIdx.x) >> 5;
    int lane = threadIdx.x & 31;
    if (warp >= N) return;
    const float* a = A + (size_t)warp * D;
    const float* b = B + (size_t)warp * D;
    float s = 0.0f;
#pragma unroll 8
    for (int k = lane; k < D; k += 32) s = fmaf(a[k], b[k], s);
#pragma unroll
    for (int off = 16; off > 0; off >>= 1)
        s += __shfl_xor_sync(0xffffffffu, s, off);
    if (lane == 0) g_diag[warp] = (*scale_p) * s;
}

// ---------------------------------------------------------------------------
// Combine 64 partials per row and per col into lse, subtract diag, reduce.
// ---------------------------------------------------------------------------
__global__ void reduce_kernel() {
    int i = blockIdx.x * blockDim.x + threadIdx.x;  // 0..N-1

    float m = -INFINITY, s = 0.0f;
#pragma unroll 4
    for (int t = 0; t < NT; t++) {
        float tm = g_rowM[(size_t)i * NT + t];
        float ts = g_rowS[(size_t)i * NT + t];
        float nm = fmaxf(m, tm);
        s = s * expf(m - nm) + ts * expf(tm - nm);
        m = nm;
    }
    float lse_r = m + logf(s);

    m = -INFINITY; s = 0.0f;
#pragma unroll 4
    for (int t = 0; t < NT; t++) {
        float tm = g_colM[(size_t)i * NT + t];
        float ts = g_colS[(size_t)i * NT + t];
        float nm = fmaxf(m, tm);
        s = s * expf(m - nm) + ts * expf(tm - nm);
        m = nm;
    }
    float lse_c = m + logf(s);

    float v = lse_r + lse_c - 2.0f * g_diag[i];

    // block reduce
    __shared__ float sm[256];
    sm[threadIdx.x] = v;
    __syncthreads();
    for (int off = 128; off > 0; off >>= 1) {
        if (threadIdx.x < off) sm[threadIdx.x] += sm[threadIdx.x + off];
        __syncthreads();
    }
    if (threadIdx.x == 0) atomicAdd(&g_acc, (double)sm[0]);
}

__global__ void final_kernel(float* out) {
    // loss = 0.5*(mean(lse_row - diag) + mean(lse_col - diag)) = sum(v)/(2N)
    out[0] = (float)(g_acc / (2.0 * (double)N));
}

// ---------------------------------------------------------------------------
extern "C" void kernel_launch(void* const* d_in, const int* in_sizes, int n_in,
                              void* d_out, int out_size) {
    const float* img   = (const float*)d_in[0];
    const float* txt   = (const float*)d_in[1];
    const float* scale = (const float*)d_in[2];
    float* out = (float*)d_out;

    init_kernel<<<1, 1>>>();

    dim3 grid(NT, NT);
    gemm_lse_kernel<<<grid, 256>>>(img, txt, scale);

    // 8192 warps, 8 warps per block
    diag_kernel<<<N / 8, 256>>>(img, txt, scale);

    reduce_kernel<<<N / 256, 256>>>();

    final_kernel<<<1, 1>>>(out);
}

// round 4
// speedup vs baseline: 5.0872x; 5.0872x over previous
#include <cuda_runtime.h>
#include <cuda_bf16.h>
#include <math.h>
#include <stdint.h>

#define N 8192
#define D 1024
#define BM 128
#define BN 128
#define BK 32
#define NT (N / 128)        // 64 tiles in each direction
#define NCHUNK (D / BK)     // 32 k-chunks
#define ROWB 80             // padded smem row stride in bytes (32 bf16 + 8 pad)
#define STAGE_BYTES (2 * 128 * ROWB)   // A(10240) + B(10240) = 20480
#define DSMEM_BYTES (4 * STAGE_BYTES)  // 81920

// ---------------------------------------------------------------------------
// Device scratch (no allocations allowed)
// ---------------------------------------------------------------------------
__device__ __nv_bfloat16 g_Abf[N * D];
__device__ __nv_bfloat16 g_Bbf[N * D];
__device__ float g_rowM[N * NT];
__device__ float g_rowS[N * NT];
__device__ float g_colM[N * NT];
__device__ float g_colS[N * NT];
__device__ float g_diag[N];
__device__ double g_acc;

// ---------------------------------------------------------------------------
// Portable PTX helpers (all sm_80/sm_90 baseline -> fine under compute_103)
// ---------------------------------------------------------------------------
__device__ __forceinline__ uint32_t smem_u32(const void* p) {
    uint32_t a;
    asm("{ .reg .u64 t; cvta.to.shared.u64 t, %1; cvt.u32.u64 %0, t; }" : "=r"(a) : "l"(p));
    return a;
}

#define CP_ASYNC16(sa, gp) \
    asm volatile("cp.async.cg.shared.global [%0], [%1], 16;" :: "r"((uint32_t)(sa)), "l"(gp) : "memory")
#define CP_COMMIT() asm volatile("cp.async.commit_group;" ::: "memory")
#define CP_WAIT3()  asm volatile("cp.async.wait_group 3;" ::: "memory")

__device__ __forceinline__ void ldsm_x4(uint32_t* r, uint32_t addr) {
    asm volatile("ldmatrix.sync.aligned.m8n8.x4.shared.b16 {%0,%1,%2,%3}, [%4];"
                 : "=r"(r[0]), "=r"(r[1]), "=r"(r[2]), "=r"(r[3]) : "r"(addr));
}

__device__ __forceinline__ void mma_bf16(float* d, const uint32_t* a, uint32_t b0, uint32_t b1) {
    asm volatile(
        "mma.sync.aligned.m16n8k16.row.col.f32.bf16.bf16.f32 "
        "{%0,%1,%2,%3}, {%4,%5,%6,%7}, {%8,%9}, {%0,%1,%2,%3};"
        : "+f"(d[0]), "+f"(d[1]), "+f"(d[2]), "+f"(d[3])
        : "r"(a[0]), "r"(a[1]), "r"(a[2]), "r"(a[3]), "r"(b0), "r"(b1));
}

// ---------------------------------------------------------------------------
__global__ void init_kernel() { g_acc = 0.0; }

// fp32 -> bf16 (RN) for both inputs
__global__ void convert_kernel(const float* __restrict__ A, const float* __restrict__ B) {
    int i = blockIdx.x * blockDim.x + threadIdx.x;
    float4 a = ((const float4*)A)[i];
    float4 b = ((const float4*)B)[i];
    __nv_bfloat162* oa = (__nv_bfloat162*)g_Abf;
    __nv_bfloat162* ob = (__nv_bfloat162*)g_Bbf;
    oa[2 * i]     = __floats2bfloat162_rn(a.x, a.y);
    oa[2 * i + 1] = __floats2bfloat162_rn(a.z, a.w);
    ob[2 * i]     = __floats2bfloat162_rn(b.x, b.y);
    ob[2 * i + 1] = __floats2bfloat162_rn(b.z, b.w);
}

// ---------------------------------------------------------------------------
// bf16 tensor-core GEMM (128x128 tile, mma.sync) + fused LSE partials
// ---------------------------------------------------------------------------
__device__ __forceinline__ void prefetch_chunk(const __nv_bfloat16* Ag, const __nv_bfloat16* Bg,
                                               uint32_t sbase, int tid, int c) {
    uint32_t st = sbase + (uint32_t)(c & 3) * STAGE_BYTES;
    int k0 = c * BK;
#pragma unroll
    for (int j = 0; j < 4; j++) {
        int idx = tid + j * 256;           // 0..1023
        int r = (idx >> 2) & 127;
        int g = idx & 3;
        if (idx < 512)
            CP_ASYNC16(st + r * ROWB + g * 16, Ag + (size_t)r * D + k0 + g * 8);
        else
            CP_ASYNC16(st + 10240 + r * ROWB + g * 16, Bg + (size_t)r * D + k0 + g * 8);
    }
    CP_COMMIT();
}

__global__ void __launch_bounds__(256, 2)
gemm_lse_mma(const float* __restrict__ scale_p) {
    extern __shared__ char dsm[];
    __shared__ float s_red[8];
    __shared__ float s_rows[4][128];
    __shared__ float s_cols[2][128];

    const int tid = threadIdx.x;
    const int wid = tid >> 5;
    const int lane = tid & 31;
    const int wm = wid & 1;    // M half (rows wm*64 .. +64)
    const int wn = wid >> 1;   // N quarter (cols wn*32 .. +32)
    const int bx = blockIdx.x;
    const int by = blockIdx.y;

    const uint32_t sbase = smem_u32(dsm);
    const __nv_bfloat16* Ag = g_Abf + (size_t)by * BM * D;
    const __nv_bfloat16* Bg = g_Bbf + (size_t)bx * BN * D;

    float acc[4][4][4];
#pragma unroll
    for (int mt = 0; mt < 4; mt++)
#pragma unroll
        for (int nt = 0; nt < 4; nt++)
#pragma unroll
            for (int i = 0; i < 4; i++) acc[mt][nt][i] = 0.0f;

    // ldmatrix per-lane base offsets (row = lane&15, 16B chunk = lane>>4)
    const uint32_t aOff = sbase + (uint32_t)((lane & 15) * ROWB + (lane >> 4) * 16 + wm * 64 * ROWB);
    const uint32_t bOff = sbase + 10240u + (uint32_t)((lane & 15) * ROWB + (lane >> 4) * 16 + wn * 32 * ROWB);

    prefetch_chunk(Ag, Bg, sbase, tid, 0);
    prefetch_chunk(Ag, Bg, sbase, tid, 1);
    prefetch_chunk(Ag, Bg, sbase, tid, 2);

    for (int c = 0; c < NCHUNK; c++) {
        if (c + 3 < NCHUNK) prefetch_chunk(Ag, Bg, sbase, tid, c + 3);
        else CP_COMMIT();
        CP_WAIT3();            // chunk c resident
        __syncthreads();

        const uint32_t stoff = (uint32_t)(c & 3) * STAGE_BYTES;
#pragma unroll
        for (int ks = 0; ks < 2; ks++) {
            uint32_t afr[4][4];
#pragma unroll
            for (int mt = 0; mt < 4; mt++)
                ldsm_x4(afr[mt], aOff + stoff + (uint32_t)(mt * 16 * ROWB + ks * 32));
            uint32_t bfr[2][4];
#pragma unroll
            for (int nt2 = 0; nt2 < 2; nt2++)
                ldsm_x4(bfr[nt2], bOff + stoff + (uint32_t)(nt2 * 16 * ROWB + ks * 32));
#pragma unroll
            for (int mt = 0; mt < 4; mt++)
#pragma unroll
                for (int nt = 0; nt < 4; nt++)
                    mma_bf16(acc[mt][nt], afr[mt],
                             bfr[nt >> 1][nt & 1], bfr[nt >> 1][(nt & 1) + 2]);
        }
        __syncthreads();       // protect stage (c-1)&3 reuse by next iter's prefetch
    }

    // ---- Fused epilogue: per-tile max, exp, row/col partial sums ----
    const float scale = __ldg(scale_p);

#pragma unroll
    for (int mt = 0; mt < 4; mt++)
#pragma unroll
        for (int nt = 0; nt < 4; nt++)
#pragma unroll
            for (int i = 0; i < 4; i++) acc[mt][nt][i] *= scale;

    float m = -INFINITY;
#pragma unroll
    for (int mt = 0; mt < 4; mt++)
#pragma unroll
        for (int nt = 0; nt < 4; nt++)
#pragma unroll
            for (int i = 0; i < 4; i++) m = fmaxf(m, acc[mt][nt][i]);
#pragma unroll
    for (int off = 16; off > 0; off >>= 1)
        m = fmaxf(m, __shfl_xor_sync(0xffffffffu, m, off));
    if (lane == 0) s_red[wid] = m;
    __syncthreads();
    float Mt = s_red[0];
#pragma unroll
    for (int w = 1; w < 8; w++) Mt = fmaxf(Mt, s_red[w]);

#pragma unroll
    for (int mt = 0; mt < 4; mt++)
#pragma unroll
        for (int nt = 0; nt < 4; nt++)
#pragma unroll
            for (int i = 0; i < 4; i++)
                acc[mt][nt][i] = __expf(acc[mt][nt][i] - Mt);

    // Row partial sums. Accum layout: reg {0,1}: row g=lane>>2, cols 2q,2q+1
    // (q=lane&3); reg {2,3}: row g+8.
#pragma unroll
    for (int mt = 0; mt < 4; mt++)
#pragma unroll
        for (int half = 0; half < 2; half++) {
            float rs = 0.0f;
#pragma unroll
            for (int nt = 0; nt < 4; nt++)
                rs += acc[mt][nt][half * 2] + acc[mt][nt][half * 2 + 1];
            rs += __shfl_xor_sync(0xffffffffu, rs, 1);
            rs += __shfl_xor_sync(0xffffffffu, rs, 2);
            if ((lane & 3) == 0)
                s_rows[wn][wm * 64 + mt * 16 + half * 8 + (lane >> 2)] = rs;
        }

    // Col partial sums
#pragma unroll
    for (int nt = 0; nt < 4; nt++)
#pragma unroll
        for (int cc = 0; cc < 2; cc++) {
            float cs = 0.0f;
#pragma unroll
            for (int mt = 0; mt < 4; mt++)
                cs += acc[mt][nt][cc] + acc[mt][nt][cc + 2];
            cs += __shfl_xor_sync(0xffffffffu, cs, 4);
            cs += __shfl_xor_sync(0xffffffffu, cs, 8);
            cs += __shfl_xor_sync(0xffffffffu, cs, 16);
            if (lane < 4)
                s_cols[wm][wn * 32 + nt * 8 + (lane & 3) * 2 + cc] = cs;
        }
    __syncthreads();

    if (tid < 128) {
        float rs = s_rows[0][tid] + s_rows[1][tid] + s_rows[2][tid] + s_rows[3][tid];
        size_t gr = (size_t)(by * BM + tid) * NT + bx;
        g_rowM[gr] = Mt;
        g_rowS[gr] = rs;
        float cs = s_cols[0][tid] + s_cols[1][tid];
        size_t gc = (size_t)(bx * BN + tid) * NT + by;
        g_colM[gc] = Mt;
        g_colS[gc] = cs;
    }
}

// ---------------------------------------------------------------------------
// Diagonal: diag[i] = scale * dot(img[i], txt[i]) in fp32. One warp per row.
// ---------------------------------------------------------------------------
__global__ void diag_kernel(const float* __restrict__ A, const float* __restrict__ B,
                            const float* __restrict__ scale_p) {
    int warp = (blockIdx.x * blockDim.x + threadIdx.x) >> 5;
    int lane = threadIdx.x & 31;
    if (warp >= N) return;
    const float* a = A + (size_t)warp * D;
    const float* b = B + (size_t)warp * D;
    float s = 0.0f;
#pragma unroll 8
    for (int k = lane; k < D; k += 32) s = fmaf(a[k], b[k], s);
#pragma unroll
    for (int off = 16; off > 0; off >>= 1)
        s += __shfl_xor_sync(0xffffffffu, s, off);
    if (lane == 0) g_diag[warp] = __ldg(scale_p) * s;
}

// ---------------------------------------------------------------------------
// Combine partials -> lse per row/col, subtract diag, reduce to scalar.
// ---------------------------------------------------------------------------
__global__ void reduce_kernel() {
    int i = blockIdx.x * blockDim.x + threadIdx.x;

    float m = -INFINITY, s = 0.0f;
#pragma unroll 4
    for (int t = 0; t < NT; t++) {
        float tm = g_rowM[(size_t)i * NT + t];
        float ts = g_rowS[(size_t)i * NT + t];
        float nm = fmaxf(m, tm);
        s = s * expf(m - nm) + ts * expf(tm - nm);
        m = nm;
    }
    float lse_r = m + logf(s);

    m = -INFINITY; s = 0.0f;
#pragma unroll 4
    for (int t = 0; t < NT; t++) {
        float tm = g_colM[(size_t)i * NT + t];
        float ts = g_colS[(size_t)i * NT + t];
        float nm = fmaxf(m, tm);
        s = s * expf(m - nm) + ts * expf(tm - nm);
        m = nm;
    }
    float lse_c = m + logf(s);

    float v = lse_r + lse_c - 2.0f * g_diag[i];

    __shared__ float sm[256];
    sm[threadIdx.x] = v;
    __syncthreads();
    for (int off = 128; off > 0; off >>= 1) {
        if (threadIdx.x < off) sm[threadIdx.x] += sm[threadIdx.x + off];
        __syncthreads();
    }
    if (threadIdx.x == 0) atomicAdd(&g_acc, (double)sm[0]);
}

__global__ void final_kernel(float* out) {
    out[0] = (float)(g_acc / (2.0 * (double)N));
}

// ---------------------------------------------------------------------------
extern "C" void kernel_launch(void* const* d_in, const int* in_sizes, int n_in,
                              void* d_out, int out_size) {
    const float* img   = (const float*)d_in[0];
    const float* txt   = (const float*)d_in[1];
    const float* scale = (const float*)d_in[2];
    float* out = (float*)d_out;

    cudaFuncSetAttribute(gemm_lse_mma, cudaFuncAttributeMaxDynamicSharedMemorySize, DSMEM_BYTES);

    init_kernel<<<1, 1>>>();
    convert_kernel<<<(N * D / 4) / 256, 256>>>(img, txt);

    dim3 grid(NT, NT);  // 64 x 64
    gemm_lse_mma<<<grid, 256, DSMEM_BYTES>>>(scale);

    diag_kernel<<<N / 8, 256>>>(img, txt, scale);
    reduce_kernel<<<N / 256, 256>>>();
    final_kernel<<<1, 1>>>(out);
}

// round 5
// speedup vs baseline: 5.3030x; 1.0424x over previous
#include <cuda_runtime.h>
#include <cuda_bf16.h>
#include <math.h>
#include <stdint.h>

#define N 8192
#define D 1024
#define BM 128
#define BN 256
#define BK 32
#define NTX (N / BN)        // 32 col tiles
#define NTY (N / BM)        // 64 row tiles
#define NCHUNK (D / BK)     // 32 k-chunks
#define ROWB 80             // padded smem row stride (64B data + 16B pad)
#define A_BYTES (BM * ROWB)           // 10240
#define STAGE_BYTES ((BM + BN) * ROWB) // 30720
#define DSMEM_BYTES (4 * STAGE_BYTES)  // 122880

// ---------------------------------------------------------------------------
// Device scratch
// ---------------------------------------------------------------------------
__device__ __nv_bfloat16 g_Abf[N * D];
__device__ __nv_bfloat16 g_Bbf[N * D];
__device__ float g_rowM[NTX * N];   // [tile][row]  (transposed: coalesced)
__device__ float g_rowS[NTX * N];
__device__ float g_colM[NTY * N];
__device__ float g_colS[NTY * N];
__device__ float g_diag[N];
__device__ double g_acc;

// ---------------------------------------------------------------------------
// Portable PTX helpers
// ---------------------------------------------------------------------------
__device__ __forceinline__ uint32_t smem_u32(const void* p) {
    uint32_t a;
    asm("{ .reg .u64 t; cvta.to.shared.u64 t, %1; cvt.u32.u64 %0, t; }" : "=r"(a) : "l"(p));
    return a;
}

#define CP_ASYNC16(sa, gp) \
    asm volatile("cp.async.cg.shared.global [%0], [%1], 16;" :: "r"((uint32_t)(sa)), "l"(gp) : "memory")
#define CP_COMMIT() asm volatile("cp.async.commit_group;" ::: "memory")
#define CP_WAIT2()  asm volatile("cp.async.wait_group 2;" ::: "memory")

__device__ __forceinline__ void ldsm_x4(uint32_t* r, uint32_t addr) {
    asm volatile("ldmatrix.sync.aligned.m8n8.x4.shared.b16 {%0,%1,%2,%3}, [%4];"
                 : "=r"(r[0]), "=r"(r[1]), "=r"(r[2]), "=r"(r[3]) : "r"(addr));
}

__device__ __forceinline__ void mma_bf16(float* d, const uint32_t* a, uint32_t b0, uint32_t b1) {
    asm volatile(
        "mma.sync.aligned.m16n8k16.row.col.f32.bf16.bf16.f32 "
        "{%0,%1,%2,%3}, {%4,%5,%6,%7}, {%8,%9}, {%0,%1,%2,%3};"
        : "+f"(d[0]), "+f"(d[1]), "+f"(d[2]), "+f"(d[3])
        : "r"(a[0]), "r"(a[1]), "r"(a[2]), "r"(a[3]), "r"(b0), "r"(b1));
}

// ---------------------------------------------------------------------------
__global__ void init_kernel() { g_acc = 0.0; }

// fp32 -> bf16 conversion fused with diagonal dot: one block per row.
__global__ void __launch_bounds__(256)
convert_diag_kernel(const float* __restrict__ A, const float* __restrict__ B,
                    const float* __restrict__ scale_p) {
    __shared__ float s_red[8];
    const int row = blockIdx.x;
    const int tid = threadIdx.x;
    const size_t base = (size_t)row * D + tid * 4;

    float4 a = *(const float4*)(A + base);
    float4 b = *(const float4*)(B + base);

    __nv_bfloat162* oa = (__nv_bfloat162*)(g_Abf + base);
    __nv_bfloat162* ob = (__nv_bfloat162*)(g_Bbf + base);
    oa[0] = __floats2bfloat162_rn(a.x, a.y);
    oa[1] = __floats2bfloat162_rn(a.z, a.w);
    ob[0] = __floats2bfloat162_rn(b.x, b.y);
    ob[1] = __floats2bfloat162_rn(b.z, b.w);

    float s = a.x * b.x + a.y * b.y + a.z * b.z + a.w * b.w;
#pragma unroll
    for (int off = 16; off > 0; off >>= 1)
        s += __shfl_xor_sync(0xffffffffu, s, off);
    if ((tid & 31) == 0) s_red[tid >> 5] = s;
    __syncthreads();
    if (tid == 0) {
        float t = 0.0f;
#pragma unroll
        for (int w = 0; w < 8; w++) t += s_red[w];
        g_diag[row] = __ldg(scale_p) * t;
    }
}

// ---------------------------------------------------------------------------
// 128x256 tile bf16 mma.sync GEMM + fused LSE partials. Warp tile 64x64.
// ---------------------------------------------------------------------------
__device__ __forceinline__ void prefetch_chunk(const __nv_bfloat16* Ag, const __nv_bfloat16* Bg,
                                               uint32_t sbase, int tid, int c) {
    if (c < NCHUNK) {
        uint32_t st = sbase + (uint32_t)(c & 3) * STAGE_BYTES;
        int k0 = c * BK;
#pragma unroll
        for (int j = 0; j < 6; j++) {
            int idx = tid + j * 256;          // 0..1535
            if (idx < 512) {
                int r = idx >> 2, g = idx & 3;
                CP_ASYNC16(st + r * ROWB + g * 16, Ag + (size_t)r * D + k0 + g * 8);
            } else {
                int e = idx - 512;            // 0..1023
                int r = e >> 2, g = e & 3;
                CP_ASYNC16(st + A_BYTES + r * ROWB + g * 16, Bg + (size_t)r * D + k0 + g * 8);
            }
        }
    }
    CP_COMMIT();
}

__global__ void __launch_bounds__(256, 1)
gemm_lse_mma(const float* __restrict__ scale_p) {
    extern __shared__ char dsm[];
    __shared__ float s_red[8];
    __shared__ float s_rows[4][128];
    __shared__ float s_cols[2][256];

    const int tid = threadIdx.x;
    const int wid = tid >> 5;
    const int lane = tid & 31;
    const int wm = wid & 1;    // M half  (rows wm*64 .. +64)
    const int wn = wid >> 1;   // N quarter (cols wn*64 .. +64)
    const int bx = blockIdx.x; // 0..NTX-1
    const int by = blockIdx.y; // 0..NTY-1

    const uint32_t sbase = smem_u32(dsm);
    const __nv_bfloat16* Ag = g_Abf + (size_t)by * BM * D;
    const __nv_bfloat16* Bg = g_Bbf + (size_t)bx * BN * D;

    float acc[4][8][4];
#pragma unroll
    for (int mt = 0; mt < 4; mt++)
#pragma unroll
        for (int nt = 0; nt < 8; nt++)
#pragma unroll
            for (int i = 0; i < 4; i++) acc[mt][nt][i] = 0.0f;

    const uint32_t lOff = (uint32_t)((lane & 15) * ROWB + (lane >> 4) * 16);
    const uint32_t aOff = sbase + lOff + (uint32_t)(wm * 64 * ROWB);
    const uint32_t bOff = sbase + A_BYTES + lOff + (uint32_t)(wn * 64 * ROWB);

    prefetch_chunk(Ag, Bg, sbase, tid, 0);
    prefetch_chunk(Ag, Bg, sbase, tid, 1);
    prefetch_chunk(Ag, Bg, sbase, tid, 2);

    for (int c = 0; c < NCHUNK; c++) {
        CP_WAIT2();            // chunk c resident
        __syncthreads();       // all warps done with stage (c-1)&3 reads
        prefetch_chunk(Ag, Bg, sbase, tid, c + 3);

        const uint32_t stoff = (uint32_t)(c & 3) * STAGE_BYTES;
#pragma unroll
        for (int ks = 0; ks < 2; ks++) {
            uint32_t afr[4][4];
#pragma unroll
            for (int mt = 0; mt < 4; mt++)
                ldsm_x4(afr[mt], aOff + stoff + (uint32_t)(mt * 16 * ROWB + ks * 32));
            uint32_t bfr[4][4];
#pragma unroll
            for (int q = 0; q < 4; q++)
                ldsm_x4(bfr[q], bOff + stoff + (uint32_t)(q * 16 * ROWB + ks * 32));
#pragma unroll
            for (int mt = 0; mt < 4; mt++)
#pragma unroll
                for (int nt = 0; nt < 8; nt++)
                    mma_bf16(acc[mt][nt], afr[mt],
                             bfr[nt >> 1][nt & 1], bfr[nt >> 1][(nt & 1) + 2]);
        }
    }

    // ---- Fused epilogue ----
    const float scale = __ldg(scale_p);
#pragma unroll
    for (int mt = 0; mt < 4; mt++)
#pragma unroll
        for (int nt = 0; nt < 8; nt++)
#pragma unroll
            for (int i = 0; i < 4; i++) acc[mt][nt][i] *= scale;

    float m = -INFINITY;
#pragma unroll
    for (int mt = 0; mt < 4; mt++)
#pragma unroll
        for (int nt = 0; nt < 8; nt++)
#pragma unroll
            for (int i = 0; i < 4; i++) m = fmaxf(m, acc[mt][nt][i]);
#pragma unroll
    for (int off = 16; off > 0; off >>= 1)
        m = fmaxf(m, __shfl_xor_sync(0xffffffffu, m, off));
    if (lane == 0) s_red[wid] = m;
    __syncthreads();
    float Mt = s_red[0];
#pragma unroll
    for (int w = 1; w < 8; w++) Mt = fmaxf(Mt, s_red[w]);

#pragma unroll
    for (int mt = 0; mt < 4; mt++)
#pragma unroll
        for (int nt = 0; nt < 8; nt++)
#pragma unroll
            for (int i = 0; i < 4; i++)
                acc[mt][nt][i] = __expf(acc[mt][nt][i] - Mt);

    // Row partial sums: acc reg i: rows (i>>1)*8+(lane>>2), cols (lane&3)*2+(i&1)
#pragma unroll
    for (int mt = 0; mt < 4; mt++)
#pragma unroll
        for (int half = 0; half < 2; half++) {
            float rs = 0.0f;
#pragma unroll
            for (int nt = 0; nt < 8; nt++)
                rs += acc[mt][nt][half * 2] + acc[mt][nt][half * 2 + 1];
            rs += __shfl_xor_sync(0xffffffffu, rs, 1);
            rs += __shfl_xor_sync(0xffffffffu, rs, 2);
            if ((lane & 3) == 0)
                s_rows[wn][wm * 64 + mt * 16 + half * 8 + (lane >> 2)] = rs;
        }

    // Col partial sums
#pragma unroll
    for (int nt = 0; nt < 8; nt++)
#pragma unroll
        for (int cc = 0; cc < 2; cc++) {
            float cs = 0.0f;
#pragma unroll
            for (int mt = 0; mt < 4; mt++)
                cs += acc[mt][nt][cc] + acc[mt][nt][cc + 2];
            cs += __shfl_xor_sync(0xffffffffu, cs, 4);
            cs += __shfl_xor_sync(0xffffffffu, cs, 8);
            cs += __shfl_xor_sync(0xffffffffu, cs, 16);
            if (lane < 4)
                s_cols[wm][wn * 64 + nt * 8 + (lane & 3) * 2 + cc] = cs;
        }
    __syncthreads();

    if (tid < 128) {
        float rs = s_rows[0][tid] + s_rows[1][tid] + s_rows[2][tid] + s_rows[3][tid];
        size_t gr = (size_t)bx * N + by * BM + tid;   // coalesced
        g_rowM[gr] = Mt;
        g_rowS[gr] = rs;
    }
    {
        float cs = s_cols[0][tid] + s_cols[1][tid];
        size_t gc = (size_t)by * N + bx * BN + tid;   // coalesced
        g_colM[gc] = Mt;
        g_colS[gc] = cs;
    }
}

// ---------------------------------------------------------------------------
// Combine partials -> lse per row/col, subtract diag, reduce to scalar.
// ---------------------------------------------------------------------------
__global__ void reduce_kernel() {
    int i = blockIdx.x * blockDim.x + threadIdx.x;

    float m = -INFINITY, s = 0.0f;
#pragma unroll
    for (int t = 0; t < NTX; t++) {
        float tm = g_rowM[(size_t)t * N + i];
        float ts = g_rowS[(size_t)t * N + i];
        float nm = fmaxf(m, tm);
        s = s * expf(m - nm) + ts * expf(tm - nm);
        m = nm;
    }
    float lse_r = m + logf(s);

    m = -INFINITY; s = 0.0f;
#pragma unroll
    for (int t = 0; t < NTY; t++) {
        float tm = g_colM[(size_t)t * N + i];
        float ts = g_colS[(size_t)t * N + i];
        float nm = fmaxf(m, tm);
        s = s * expf(m - nm) + ts * expf(tm - nm);
        m = nm;
    }
    float lse_c = m + logf(s);

    float v = lse_r + lse_c - 2.0f * g_diag[i];

    __shared__ float sm[256];
    sm[threadIdx.x] = v;
    __syncthreads();
    for (int off = 128; off > 0; off >>= 1) {
        if (threadIdx.x < off) sm[threadIdx.x] += sm[threadIdx.x + off];
        __syncthreads();
    }
    if (threadIdx.x == 0) atomicAdd(&g_acc, (double)sm[0]);
}

__global__ void final_kernel(float* out) {
    out[0] = (float)(g_acc / (2.0 * (double)N));
}

// ---------------------------------------------------------------------------
extern "C" void kernel_launch(void* const* d_in, const int* in_sizes, int n_in,
                              void* d_out, int out_size) {
    const float* img   = (const float*)d_in[0];
    const float* txt   = (const float*)d_in[1];
    const float* scale = (const float*)d_in[2];
    float* out = (float*)d_out;

    cudaFuncSetAttribute(gemm_lse_mma, cudaFuncAttributeMaxDynamicSharedMemorySize, DSMEM_BYTES);

    init_kernel<<<1, 1>>>();
    convert_diag_kernel<<<N, 256>>>(img, txt, scale);

    dim3 grid(NTX, NTY);  // 32 x 64
    gemm_lse_mma<<<grid, 256, DSMEM_BYTES>>>(scale);

    reduce_kernel<<<N / 256, 256>>>();
    final_kernel<<<1, 1>>>(out);
}